// round 16
// baseline (speedup 1.0000x reference)
#include <cuda_runtime.h>
#include <math.h>
#include <stdint.h>

#define BS 32
#define NS 65536
#define NF 128
#define CHUNK 8
#define NCH (NS / CHUNK)      // 8192
#define SRf 48000.0f
#define STAB 0.999f
#define POSC (127.0f / 65535.0f)
#define R48 (1.0f / 48000.0f)

// Output plane offsets (elements of BS*NS):
// dry=0, wet=1, env=2, y_ab=3, a_coeff3=4..6, b_coeff=7..9, y_a=10

__device__ float4 g_frame[BS * NF * 2];
__device__ float  g_chunk[BS * NCH * 6];  // u1,v1,u2,v2,yp1,yp2
__device__ float2 g_init[BS * NCH];

__device__ __forceinline__ float div_cr(float x, float d, float r) {
    float q0 = __fmul_rn(x, r);
    float rem = fmaf(-q0, d, x);
    return fmaf(rem, r, q0);
}

// ---- XLA rational tanh: CR-div version (coeff path) ----
__device__ __forceinline__ float xla_tanh_cr(float x) {
    const float kClamp = 7.90531110763549805f;
    float xc = fminf(fmaxf(x, -kClamp), kClamp);
    float x2 = __fmul_rn(xc, xc);
    float p = __fadd_rn(2.00018790482477e-13f, __fmul_rn(x2, -2.76076847742355e-16f));
    p = __fadd_rn(-8.60467152213735e-11f, __fmul_rn(x2, p));
    p = __fadd_rn(5.12229709037114e-08f,  __fmul_rn(x2, p));
    p = __fadd_rn(1.48572235717979e-05f,  __fmul_rn(x2, p));
    p = __fadd_rn(6.37261928875436e-04f,  __fmul_rn(x2, p));
    p = __fadd_rn(4.89352455891786e-03f,  __fmul_rn(x2, p));
    float num = __fmul_rn(xc, p);
    float q = __fadd_rn(1.18534705686654e-04f, __fmul_rn(x2, 1.19825839466702e-06f));
    q = __fadd_rn(2.26843463243900e-03f, __fmul_rn(x2, q));
    q = __fadd_rn(4.89352518554385e-03f, __fmul_rn(x2, q));
    float r = __fdiv_rn(num, q);
    return (fabsf(x) < 0.0004f) ? x : r;
}

// ---- fast-div version (per-sample path; ~2ulp) ----
__device__ __forceinline__ float xla_tanh_f(float x) {
    const float kClamp = 7.90531110763549805f;
    float xc = fminf(fmaxf(x, -kClamp), kClamp);
    float x2 = __fmul_rn(xc, xc);
    float p = __fadd_rn(2.00018790482477e-13f, __fmul_rn(x2, -2.76076847742355e-16f));
    p = __fadd_rn(-8.60467152213735e-11f, __fmul_rn(x2, p));
    p = __fadd_rn(5.12229709037114e-08f,  __fmul_rn(x2, p));
    p = __fadd_rn(1.48572235717979e-05f,  __fmul_rn(x2, p));
    p = __fadd_rn(6.37261928875436e-04f,  __fmul_rn(x2, p));
    p = __fadd_rn(4.89352455891786e-03f,  __fmul_rn(x2, p));
    float num = __fmul_rn(xc, p);
    float q = __fadd_rn(1.18534705686654e-04f, __fmul_rn(x2, 1.19825839466702e-06f));
    q = __fadd_rn(2.26843463243900e-03f, __fmul_rn(x2, q));
    q = __fadd_rn(4.89352518554385e-03f, __fmul_rn(x2, q));
    float r = __fdividef(num, q);
    return (fabsf(x) < 0.0004f) ? x : r;
}

__device__ __forceinline__ void fast_sc(float r, float& ps, float& pc, int& iq) {
    float qf = rintf(r * 0.636619772367581343f);
    float t = fmaf(qf, -1.57079637050628662109f, r);
    t = fmaf(qf, 4.37113900018624283e-8f, t);
    iq = ((int)qf) & 3;
    float t2 = t * t;
    float s = fmaf(t2, 2.7557314297e-06f, -1.9841270114e-04f);
    s = fmaf(t2, s, 8.3333337680e-03f);
    s = fmaf(t2, s, -1.6666667163e-01f);
    ps = fmaf(t * t2, s, t);
    float c = fmaf(t2, 2.4801587642e-05f, -1.3888889225e-03f);
    c = fmaf(t2, c, 4.1666667908e-02f);
    c = fmaf(t2, c, -0.5f);
    pc = fmaf(t2, c, 1.0f);
}

__device__ __forceinline__ float cum_base3(float c, unsigned v) {
    int msb = 31 - __clz(v);
    float r = c * __int_as_float((127 + msb) << 23);
#pragma unroll 1
    for (int k = msb - 1; k >= 3; k--) {
        if ((v >> k) & 1u)
            r = __fadd_rn(r, c * __int_as_float((127 + k) << 23));
    }
    return r;
}

__device__ __forceinline__ void compute_frame(const float* __restrict__ lg, float* dst) {
    float th0 = xla_tanh_cr(lg[0]);
    float a1 = __fmul_rn(__fmul_rn(2.0f, th0), STAB);
    float a1a = fabsf(a1);
    float th1 = xla_tanh_cr(lg[1]);
    float a2 = __fdiv_rn(__fadd_rn(__fmul_rn(__fmul_rn(__fsub_rn(2.0f, a1a), th1), STAB), a1a), 2.0f);
    dst[0] = a1; dst[1] = a2; dst[2] = lg[2]; dst[3] = lg[3]; dst[4] = lg[4];
}

// ---------------- K-coeff (concurrent stream): a3/b3 plane stores ----------------
__global__ void __launch_bounds__(128) k_coeff(float* __restrict__ out,
                                               const float* __restrict__ logits) {
    __shared__ float sfr[5][5];
    int tid = blockIdx.x * blockDim.x + threadIdx.x;
    int b = tid >> 13;
    int c = tid & (NCH - 1);
    int s0 = c << 3;

    int BS0 = (blockIdx.x & 63) << 10;
    float bpos0 = __fmul_rn((float)BS0, POSC);
    int f_first = min((int)floorf(bpos0), 126);
    if (threadIdx.x < 5) {
        int f = f_first + threadIdx.x;
        if (f <= 127)
            compute_frame(logits + ((size_t)(b * NF + f)) * 5, sfr[threadIdx.x]);
    }
    __syncthreads();

    float pos0 = __fmul_rn((float)s0, POSC);
    int i0s = min((int)floorf(pos0), 126);
    int r0i = i0s - f_first;
    int r2i = min(i0s + 2, 127) - f_first;
    float F0[5], F1[5], F2[5];
#pragma unroll
    for (int q = 0; q < 5; q++) { F0[q] = sfr[r0i][q]; F1[q] = sfr[r0i + 1][q]; F2[q] = sfr[r2i][q]; }

    size_t base = (size_t)b * NS + s0;
    float4* aptr = (float4*)(out + 4ull * BS * NS + base * 3);
    float4* bptr = (float4*)(out + 7ull * BS * NS + base * 3);

#pragma unroll
    for (int g = 0; g < 2; g++) {
        float a1v[4], a2v[4], b0v[4], b1v[4], b2v[4];
#pragma unroll
        for (int j = 0; j < 4; j++) {
            int i = s0 + g * 4 + j;
            float pos = __fmul_rn((float)i, POSC);
            int i0 = min((int)floorf(pos), 126);
            float frc = __fsub_rn(pos, (float)i0);
            float w0 = __fsub_rn(1.0f, frc);
            bool hi = (i0 != i0s);
            float fa1 = hi ? F1[0] : F0[0], ga1 = hi ? F2[0] : F1[0];
            float fa2 = hi ? F1[1] : F0[1], ga2 = hi ? F2[1] : F1[1];
            float fb0 = hi ? F1[2] : F0[2], gb0 = hi ? F2[2] : F1[2];
            float fb1 = hi ? F1[3] : F0[3], gb1 = hi ? F2[3] : F1[3];
            float fb2 = hi ? F1[4] : F0[4], gb2 = hi ? F2[4] : F1[4];
            a1v[j] = __fadd_rn(__fmul_rn(fa1, w0), __fmul_rn(ga1, frc));
            a2v[j] = __fadd_rn(__fmul_rn(fa2, w0), __fmul_rn(ga2, frc));
            b0v[j] = __fadd_rn(__fmul_rn(fb0, w0), __fmul_rn(gb0, frc));
            b1v[j] = __fadd_rn(__fmul_rn(fb1, w0), __fmul_rn(gb1, frc));
            b2v[j] = __fadd_rn(__fmul_rn(fb2, w0), __fmul_rn(gb2, frc));
        }
        aptr[3 * g + 0] = make_float4(1.0f, a1v[0], a2v[0], 1.0f);
        aptr[3 * g + 1] = make_float4(a1v[1], a2v[1], 1.0f, a1v[2]);
        aptr[3 * g + 2] = make_float4(a2v[2], 1.0f, a1v[3], a2v[3]);
        bptr[3 * g + 0] = make_float4(b0v[0], b1v[0], b2v[0], b0v[1]);
        bptr[3 * g + 1] = make_float4(b1v[1], b2v[1], b0v[2], b1v[2]);
        bptr[3 * g + 2] = make_float4(b2v[2], b0v[3], b1v[3], b2v[3]);
    }
}

// ---------------- K1: osc + env + a1/a2 interp + fused pass1 ----------------
__global__ void __launch_bounds__(128) k_mainp1(
        float* __restrict__ out,
        const float* __restrict__ f0_hz,
        const float* __restrict__ durp,
        const float* __restrict__ phasep,
        const float* __restrict__ logits,
        const float* __restrict__ shpp,
        const float* __restrict__ gainp,
        const float* __restrict__ alphap) {
    __shared__ float sfr[5][5];
    __shared__ float sbp[12];

    int tid = blockIdx.x * blockDim.x + threadIdx.x;
    int b = tid >> 13;
    int c = tid & (NCH - 1);
    int s0 = c << 3;

    int BS0 = (blockIdx.x & 63) << 10;
    float bpos0 = __fmul_rn((float)BS0, POSC);
    int f_first = min((int)floorf(bpos0), 126);

    if (threadIdx.x < 5) {
        int f = f_first + threadIdx.x;
        if (f <= 127)
            compute_frame(logits + ((size_t)(b * NF + f)) * 5, sfr[threadIdx.x]);
    } else if (threadIdx.x == 5) {
        float f0 = f0_hz[b];
        sbp[0] = __fdiv_rn(f0, SRf);
        sbp[1] = phasep[b];
        float partials = __fdiv_rn(12000.0f, __fmul_rn(f0, log10f(f0)));
        sbp[2] = __fmul_rn(3.14159274101257324f, partials);
        float sh = shpp[b];
        sbp[3] = sh;
        sbp[4] = __fsub_rn(1.0f, __fmul_rn(sh, 0.5f));
        sbp[5] = gainp[b];
        sbp[6] = durp[b];
        sbp[7] = alphap[b];
        sbp[8] = __fdiv_rn(1.0f, durp[b]);
    }
    __syncthreads();

    float p_phase = sbp[1], p_kk = sbp[2], p_shp = sbp[3];
    float p_sm = sbp[4], p_gain = sbp[5], p_dur = sbp[6], p_alpha = sbp[7], p_rdur = sbp[8];

    float pos0 = __fmul_rn((float)s0, POSC);
    int i0s = min((int)floorf(pos0), 126);
    int r0i = i0s - f_first;
    int r2i = min(i0s + 2, 127) - f_first;
    float Fa1_0 = sfr[r0i][0], Fa2_0 = sfr[r0i][1];
    float Fa1_1 = sfr[r0i + 1][0], Fa2_1 = sfr[r0i + 1][1];
    float Fa1_2 = sfr[r2i][0], Fa2_2 = sfr[r2i][1];

    float yp1 = 0.f, yp2 = 0.f, u1 = 1.f, u2 = 0.f, v1 = 0.f, v2 = 1.f;

    float tt0 = div_cr((float)s0, SRf, R48);
    bool alive = (tt0 <= p_dur);

    size_t base = (size_t)b * NS + s0;
    float4* dptr = (float4*)(out + base);
    float4* eptr = (float4*)(out + 2ull * BS * NS + base);

    float inc = sbp[0];
    float i4 = inc * 4.0f, i2c = inc * 2.0f;
    float baseA = 0.0f, baseB = 0.0f;
    if (alive) {
        baseA = (s0 == 0) ? 0.0f : cum_base3(inc, (unsigned)s0);
        baseB = cum_base3(inc, (unsigned)(s0 + 8));
    }

#pragma unroll
    for (int g = 0; g < 2; g++) {
        float dry4[4], env4[4];
#pragma unroll
        for (int j = 0; j < 4; j++) {
            int jj = g * 4 + j;
            int i = s0 + jj;
            if (alive) {
                unsigned l = (unsigned)(jj + 1);
                float cum = (l < 8u) ? baseA : baseB;
                if (l & 4u)  cum = __fadd_rn(cum, i4);
                if (l & 2u)  cum = __fadd_rn(cum, i2c);
                if (l & 1u)  cum = __fadd_rn(cum, inc);
                float arg = __fadd_rn(__fmul_rn(6.28318548202514648f, cum), p_phase);
                float carg = __fmul_rn(arg, 0.5f);
                float kq = rintf(__fmul_rn(carg, 0.15915494309189535f));
                float rr = fmaf(-kq, 6.28318548202514648f, carg);
                float ps, pc; int iq;
                fast_sc(rr, ps, pc, iq);
                float shh = (iq & 1) ? pc : ps; shh = (iq & 2) ? -shh : shh;
                float chh = (iq & 1) ? ps : pc; chh = ((iq + 1) & 2) ? -chh : chh;
                float cc = chh;
                float s = 2.0f * shh * chh;

                float sq = xla_tanh_f(__fmul_rn(__fmul_rn(p_kk, s), 0.5f));
                float vco = __fmul_rn(__fmul_rn(p_sm, sq),
                                      __fadd_rn(1.0f, __fmul_rn(p_shp, cc)));

                float tt = div_cr((float)i, SRf, R48);
                float ramp = __fsub_rn(1.0f, div_cr(tt, p_dur, p_rdur));
                ramp = fminf(fmaxf(ramp, 0.001f), 1.0f);
                float env = __powf(ramp, p_alpha);
                if (!(tt <= p_dur)) env = 0.0f;
                env4[j] = env;
                dry4[j] = __fmul_rn(__fmul_rn(vco, p_gain), env);
            } else {
                env4[j] = 0.0f;
                dry4[j] = 0.0f;
            }

            float pos = __fmul_rn((float)i, POSC);
            int i0 = min((int)floorf(pos), 126);
            float frc = __fsub_rn(pos, (float)i0);
            float w0 = __fsub_rn(1.0f, frc);
            bool hi = (i0 != i0s);
            float fa1 = hi ? Fa1_1 : Fa1_0, ga1 = hi ? Fa1_2 : Fa1_1;
            float fa2 = hi ? Fa2_1 : Fa2_0, ga2 = hi ? Fa2_2 : Fa2_1;
            float a1 = __fadd_rn(__fmul_rn(fa1, w0), __fmul_rn(ga1, frc));
            float a2 = __fadd_rn(__fmul_rn(fa2, w0), __fmul_rn(ga2, frc));

            float dj = dry4[j];
            float yp = fmaf(-a1, yp1, fmaf(-a2, yp2, dj));
            float uu = fmaf(-a1, u1, -(a2 * u2));
            float vv = fmaf(-a1, v1, -(a2 * v2));
            yp2 = yp1; yp1 = yp;
            u2 = u1; u1 = uu;
            v2 = v1; v1 = vv;
        }
        dptr[g] = make_float4(dry4[0], dry4[1], dry4[2], dry4[3]);
        eptr[g] = make_float4(env4[0], env4[1], env4[2], env4[3]);
    }

    float* o = g_chunk + (size_t)tid * 6;
    o[0] = u1; o[1] = v1; o[2] = u2; o[3] = v2; o[4] = yp1; o[5] = yp2;
}

#define COMPOSE_ACC(c00,c01,c10,c11,r0,r1, m00,m01,m10,m11,p0,p1) do { \
    float n00 = __fmaf_rn(c00, m00, __fmul_rn(c01, m10)); \
    float n01 = __fmaf_rn(c00, m01, __fmul_rn(c01, m11)); \
    float n10 = __fmaf_rn(c10, m00, __fmul_rn(c11, m10)); \
    float n11 = __fmaf_rn(c10, m01, __fmul_rn(c11, m11)); \
    float np0 = __fadd_rn(__fmaf_rn(c00, p0, __fmul_rn(c01, p1)), r0); \
    float np1 = __fadd_rn(__fmaf_rn(c10, p0, __fmul_rn(c11, p1)), r1); \
    m00 = n00; m01 = n01; m10 = n10; m11 = n11; p0 = np0; p1 = np1; } while (0)

// ---------------- K2: per-voice parallel scan + g_frame publish ----------------
__global__ void k_scan2(const float* __restrict__ logits) {
    extern __shared__ float sm[];
    __shared__ float wtot[8 * 6];
    __shared__ float wpre[8 * 6];
    int b = blockIdx.x;
    int tid = threadIdx.x;

    const float* raw = g_chunk + (size_t)b * NCH * 6;
    for (int idx = tid; idx < NCH * 6; idx += blockDim.x) {
        int chunk = idx / 6;
        int field = idx - chunk * 6;
        int w = chunk >> 10;
        int chr = chunk & 1023;
        int swp = ((chr & 31) << 5) | (chr >> 5);
        sm[((w << 10) + swp) * 7 + field] = raw[idx];
    }
    if (tid >= 256 && tid < 384) {
        int f = tid - 256;
        float dst[5];
        compute_frame(logits + ((size_t)(b * NF + f)) * 5, dst);
        g_frame[(b * NF + f) * 2]     = make_float4(dst[0], dst[1], dst[2], dst[3]);
        g_frame[(b * NF + f) * 2 + 1] = make_float4(dst[4], 0.f, 0.f, 0.f);
    }
    __syncthreads();

    float m00 = 1.f, m01 = 0.f, m10 = 0.f, m11 = 1.f, p0 = 0.f, p1 = 0.f;
    int w = tid >> 5, lane = tid & 31;
    if (tid < 256) {
        const float* rbase = &sm[(w << 10) * 7 + lane * 7];
#pragma unroll 1
        for (int c = 0; c < 32; c++) {
            const float* rec = rbase + (c << 5) * 7;
            COMPOSE_ACC(rec[0], rec[1], rec[2], rec[3], rec[4], rec[5],
                        m00, m01, m10, m11, p0, p1);
        }
#pragma unroll
        for (int d = 1; d < 32; d <<= 1) {
            float e00 = __shfl_up_sync(0xffffffffu, m00, d);
            float e01 = __shfl_up_sync(0xffffffffu, m01, d);
            float e10 = __shfl_up_sync(0xffffffffu, m10, d);
            float e11 = __shfl_up_sync(0xffffffffu, m11, d);
            float ep0 = __shfl_up_sync(0xffffffffu, p0, d);
            float ep1 = __shfl_up_sync(0xffffffffu, p1, d);
            if (lane >= d) {
                float n00 = __fmaf_rn(m00, e00, __fmul_rn(m01, e10));
                float n01 = __fmaf_rn(m00, e01, __fmul_rn(m01, e11));
                float n10 = __fmaf_rn(m10, e00, __fmul_rn(m11, e10));
                float n11 = __fmaf_rn(m10, e01, __fmul_rn(m11, e11));
                float np0 = __fadd_rn(__fmaf_rn(m00, ep0, __fmul_rn(m01, ep1)), p0);
                float np1 = __fadd_rn(__fmaf_rn(m10, ep0, __fmul_rn(m11, ep1)), p1);
                m00 = n00; m01 = n01; m10 = n10; m11 = n11; p0 = np0; p1 = np1;
            }
        }
        if (lane == 31) {
            wtot[w * 6 + 0] = m00; wtot[w * 6 + 1] = m01; wtot[w * 6 + 2] = m10;
            wtot[w * 6 + 3] = m11; wtot[w * 6 + 4] = p0;  wtot[w * 6 + 5] = p1;
        }
    }
    __syncthreads();
    if (tid == 0) {
        float q00 = 1.f, q01 = 0.f, q10 = 0.f, q11 = 1.f, qp0 = 0.f, qp1 = 0.f;
#pragma unroll
        for (int ww = 0; ww < 8; ww++) {
            wpre[ww * 6 + 0] = q00; wpre[ww * 6 + 1] = q01; wpre[ww * 6 + 2] = q10;
            wpre[ww * 6 + 3] = q11; wpre[ww * 6 + 4] = qp0; wpre[ww * 6 + 5] = qp1;
            COMPOSE_ACC(wtot[ww * 6 + 0], wtot[ww * 6 + 1], wtot[ww * 6 + 2],
                        wtot[ww * 6 + 3], wtot[ww * 6 + 4], wtot[ww * 6 + 5],
                        q00, q01, q10, q11, qp0, qp1);
        }
    }
    __syncthreads();
    if (tid < 256) {
        float e00 = __shfl_up_sync(0xffffffffu, m00, 1);
        float e01 = __shfl_up_sync(0xffffffffu, m01, 1);
        float e10 = __shfl_up_sync(0xffffffffu, m10, 1);
        float e11 = __shfl_up_sync(0xffffffffu, m11, 1);
        float ep0 = __shfl_up_sync(0xffffffffu, p0, 1);
        float ep1 = __shfl_up_sync(0xffffffffu, p1, 1);
        if (lane == 0) { e00 = 1.f; e01 = 0.f; e10 = 0.f; e11 = 1.f; ep0 = 0.f; ep1 = 0.f; }
        float Pp0 = wpre[w * 6 + 4], Pp1 = wpre[w * 6 + 5];
        float s0 = __fadd_rn(__fmaf_rn(e00, Pp0, __fmul_rn(e01, Pp1)), ep0);
        float s1 = __fadd_rn(__fmaf_rn(e10, Pp0, __fmul_rn(e11, Pp1)), ep1);

        const float* rbase = &sm[(w << 10) * 7 + lane * 7];
        int cbase = (b << 13) + tid * 32;
#pragma unroll 1
        for (int c = 0; c < 32; c++) {
            g_init[cbase + c] = make_float2(s0, s1);
            const float* rec = rbase + (c << 5) * 7;
            float ns0 = __fadd_rn(__fmaf_rn(rec[0], s0, __fmul_rn(rec[1], s1)), rec[4]);
            float ns1 = __fadd_rn(__fmaf_rn(rec[2], s0, __fmul_rn(rec[3], s1)), rec[5]);
            s0 = ns0; s1 = ns1;
        }
    }
}

// ---------------- K3: pass 2 — coeff recompute + IIR + FIR + tanh (lean) ----------------
__global__ void __launch_bounds__(128) k_pass2(float* __restrict__ out,
                                               const float* __restrict__ distp) {
    int tid = blockIdx.x * blockDim.x + threadIdx.x;
    if (tid >= BS * NCH) return;
    int b = tid >> 13;
    int c = tid & (NCH - 1);
    int s0 = c << 3;
    size_t base = (size_t)b * NS + s0;
    const float* dry = out + base;
    float* w_wet = out + 1ull * BS * NS + base;
    float* w_yab = out + 3ull * BS * NS + base;
    float* w_ya = out + 10ull * BS * NS + base;

    float pos0 = __fmul_rn((float)s0, POSC);
    int i0s = min((int)floorf(pos0), 126);
    int i2x = min(i0s + 2, 127);
    float4 F0a = g_frame[(b * NF + i0s) * 2],     F0b = g_frame[(b * NF + i0s) * 2 + 1];
    float4 F1a = g_frame[(b * NF + i0s + 1) * 2], F1b = g_frame[(b * NF + i0s + 1) * 2 + 1];
    float4 F2a = g_frame[(b * NF + i2x) * 2],     F2b = g_frame[(b * NF + i2x) * 2 + 1];

    float2 ini = g_init[tid];
    float y1 = ini.x, y2 = ini.y;
    float dg = distp[b];

#pragma unroll
    for (int g = 0; g < 2; g++) {
        float4 xq = ((const float4*)dry)[g];
        float xs[4] = {xq.x, xq.y, xq.z, xq.w};
        float ya[4], yb[4], wt[4];
#pragma unroll
        for (int j = 0; j < 4; j++) {
            int i = s0 + g * 4 + j;
            float pos = __fmul_rn((float)i, POSC);
            int i0 = min((int)floorf(pos), 126);
            float frc = __fsub_rn(pos, (float)i0);
            float w0 = __fsub_rn(1.0f, frc);
            bool hi = (i0 != i0s);
            float4 fA = hi ? F1a : F0a;
            float4 fB = hi ? F1b : F0b;
            float4 gA = hi ? F2a : F1a;
            float4 gB = hi ? F2b : F1b;
            float a1 = __fadd_rn(__fmul_rn(fA.x, w0), __fmul_rn(gA.x, frc));
            float a2 = __fadd_rn(__fmul_rn(fA.y, w0), __fmul_rn(gA.y, frc));
            float c0 = __fadd_rn(__fmul_rn(fA.z, w0), __fmul_rn(gA.z, frc));
            float c1 = __fadd_rn(__fmul_rn(fA.w, w0), __fmul_rn(gA.w, frc));
            float c2 = __fadd_rn(__fmul_rn(fB.x, w0), __fmul_rn(gB.x, frc));

            float y = __fsub_rn(__fsub_rn(xs[j], __fmul_rn(a1, y1)), __fmul_rn(a2, y2));
            float v = __fadd_rn(__fadd_rn(__fmul_rn(c0, y), __fmul_rn(c1, y1)),
                                __fmul_rn(c2, y2));
            ya[j] = y; yb[j] = v;
            wt[j] = xla_tanh_f(__fmul_rn(v, dg));
            y2 = y1; y1 = y;
        }
        ((float4*)w_ya)[g] = make_float4(ya[0], ya[1], ya[2], ya[3]);
        ((float4*)w_yab)[g] = make_float4(yb[0], yb[1], yb[2], yb[3]);
        ((float4*)w_wet)[g] = make_float4(wt[0], wt[1], wt[2], wt[3]);
    }
}

extern "C" void kernel_launch(void* const* d_in, const int* in_sizes, int n_in,
                              void* d_out, int out_size) {
    const float* f0_hz = (const float*)d_in[0];
    const float* note_on = (const float*)d_in[1];
    const float* phase = (const float*)d_in[2];
    const float* logits = (const float*)d_in[3];
    const float* osc_shape = (const float*)d_in[4];
    const float* osc_gain = (const float*)d_in[5];
    const float* dist_gain = (const float*)d_in[6];
    const float* learned_alpha = (const float*)d_in[7];
    float* out = (float*)d_out;

    static int inited = 0;
    static cudaStream_t s2;
    static cudaEvent_t evFork, evJoin;
    const int scan_smem = NCH * 7 * sizeof(float);   // 229376 B dynamic
    if (!inited) {
        cudaFuncSetAttribute(k_scan2, cudaFuncAttributeMaxDynamicSharedMemorySize, scan_smem);
        cudaStreamCreateWithFlags(&s2, cudaStreamNonBlocking);
        cudaEventCreateWithFlags(&evFork, cudaEventDisableTiming);
        cudaEventCreateWithFlags(&evJoin, cudaEventDisableTiming);
        inited = 1;
    }

    // fork: coeff planes (depend only on logits) run concurrently on s2
    cudaEventRecord(evFork, 0);
    cudaStreamWaitEvent(s2, evFork, 0);
    k_coeff<<<(BS * NCH + 127) / 128, 128, 0, s2>>>(out, logits);
    cudaEventRecord(evJoin, s2);

    k_mainp1<<<(BS * NCH + 127) / 128, 128>>>(out, f0_hz, note_on, phase, logits,
                                              osc_shape, osc_gain, learned_alpha);
    k_scan2<<<BS, 1024, scan_smem>>>(logits);

    // join before pass2 (pass2 doesn't touch a/b planes, but join keeps the
    // graph's output complete before the final kernel finishes)
    cudaStreamWaitEvent(0, evJoin, 0);
    k_pass2<<<(BS * NCH + 127) / 128, 128>>>(out, dist_gain);
}

// round 17
// speedup vs baseline: 1.0172x; 1.0172x over previous
#include <cuda_runtime.h>
#include <math.h>
#include <stdint.h>

#define BS 32
#define NS 65536
#define NF 128
#define CHUNK 8
#define NCH (NS / CHUNK)      // 8192
#define SRf 48000.0f
#define STAB 0.999f
#define POSC (127.0f / 65535.0f)
#define R48 (1.0f / 48000.0f)

// Output plane offsets (elements of BS*NS):
// dry=0, wet=1, env=2, y_ab=3, a_coeff3=4..6, b_coeff=7..9, y_a=10

__device__ float4 g_frame[BS * NF * 2];
__device__ float  g_chunk[BS * NCH * 6];  // u1,v1,u2,v2,yp1,yp2
__device__ float2 g_init[BS * NCH];

__device__ __forceinline__ float div_cr(float x, float d, float r) {
    float q0 = __fmul_rn(x, r);
    float rem = fmaf(-q0, d, x);
    return fmaf(rem, r, q0);
}

// ---- XLA rational tanh: CR-div version (coeff path) ----
__device__ __forceinline__ float xla_tanh_cr(float x) {
    const float kClamp = 7.90531110763549805f;
    float xc = fminf(fmaxf(x, -kClamp), kClamp);
    float x2 = __fmul_rn(xc, xc);
    float p = __fadd_rn(2.00018790482477e-13f, __fmul_rn(x2, -2.76076847742355e-16f));
    p = __fadd_rn(-8.60467152213735e-11f, __fmul_rn(x2, p));
    p = __fadd_rn(5.12229709037114e-08f,  __fmul_rn(x2, p));
    p = __fadd_rn(1.48572235717979e-05f,  __fmul_rn(x2, p));
    p = __fadd_rn(6.37261928875436e-04f,  __fmul_rn(x2, p));
    p = __fadd_rn(4.89352455891786e-03f,  __fmul_rn(x2, p));
    float num = __fmul_rn(xc, p);
    float q = __fadd_rn(1.18534705686654e-04f, __fmul_rn(x2, 1.19825839466702e-06f));
    q = __fadd_rn(2.26843463243900e-03f, __fmul_rn(x2, q));
    q = __fadd_rn(4.89352518554385e-03f, __fmul_rn(x2, q));
    float r = __fdiv_rn(num, q);
    return (fabsf(x) < 0.0004f) ? x : r;
}

// ---- fast-div version (per-sample path; ~2ulp) ----
__device__ __forceinline__ float xla_tanh_f(float x) {
    const float kClamp = 7.90531110763549805f;
    float xc = fminf(fmaxf(x, -kClamp), kClamp);
    float x2 = __fmul_rn(xc, xc);
    float p = __fadd_rn(2.00018790482477e-13f, __fmul_rn(x2, -2.76076847742355e-16f));
    p = __fadd_rn(-8.60467152213735e-11f, __fmul_rn(x2, p));
    p = __fadd_rn(5.12229709037114e-08f,  __fmul_rn(x2, p));
    p = __fadd_rn(1.48572235717979e-05f,  __fmul_rn(x2, p));
    p = __fadd_rn(6.37261928875436e-04f,  __fmul_rn(x2, p));
    p = __fadd_rn(4.89352455891786e-03f,  __fmul_rn(x2, p));
    float num = __fmul_rn(xc, p);
    float q = __fadd_rn(1.18534705686654e-04f, __fmul_rn(x2, 1.19825839466702e-06f));
    q = __fadd_rn(2.26843463243900e-03f, __fmul_rn(x2, q));
    q = __fadd_rn(4.89352518554385e-03f, __fmul_rn(x2, q));
    float r = __fdividef(num, q);
    return (fabsf(x) < 0.0004f) ? x : r;
}

__device__ __forceinline__ void fast_sc(float r, float& ps, float& pc, int& iq) {
    float qf = rintf(r * 0.636619772367581343f);
    float t = fmaf(qf, -1.57079637050628662109f, r);
    t = fmaf(qf, 4.37113900018624283e-8f, t);
    iq = ((int)qf) & 3;
    float t2 = t * t;
    float s = fmaf(t2, 2.7557314297e-06f, -1.9841270114e-04f);
    s = fmaf(t2, s, 8.3333337680e-03f);
    s = fmaf(t2, s, -1.6666667163e-01f);
    ps = fmaf(t * t2, s, t);
    float c = fmaf(t2, 2.4801587642e-05f, -1.3888889225e-03f);
    c = fmaf(t2, c, 4.1666667908e-02f);
    c = fmaf(t2, c, -0.5f);
    pc = fmaf(t2, c, 1.0f);
}

__device__ __forceinline__ float cum_base3(float c, unsigned v) {
    int msb = 31 - __clz(v);
    float r = c * __int_as_float((127 + msb) << 23);
#pragma unroll 1
    for (int k = msb - 1; k >= 3; k--) {
        if ((v >> k) & 1u)
            r = __fadd_rn(r, c * __int_as_float((127 + k) << 23));
    }
    return r;
}

__device__ __forceinline__ void compute_frame(const float* __restrict__ lg, float* dst) {
    float th0 = xla_tanh_cr(lg[0]);
    float a1 = __fmul_rn(__fmul_rn(2.0f, th0), STAB);
    float a1a = fabsf(a1);
    float th1 = xla_tanh_cr(lg[1]);
    float a2 = __fdiv_rn(__fadd_rn(__fmul_rn(__fmul_rn(__fsub_rn(2.0f, a1a), th1), STAB), a1a), 2.0f);
    dst[0] = a1; dst[1] = a2; dst[2] = lg[2]; dst[3] = lg[3]; dst[4] = lg[4];
}

// ---------------- K-coeff (concurrent with scan): a3/b3 plane stores ----------------
__global__ void __launch_bounds__(128) k_coeff(float* __restrict__ out,
                                               const float* __restrict__ logits) {
    __shared__ float sfr[5][5];
    int tid = blockIdx.x * blockDim.x + threadIdx.x;
    int b = tid >> 13;
    int c = tid & (NCH - 1);
    int s0 = c << 3;

    int BS0 = (blockIdx.x & 63) << 10;
    float bpos0 = __fmul_rn((float)BS0, POSC);
    int f_first = min((int)floorf(bpos0), 126);
    if (threadIdx.x < 5) {
        int f = f_first + threadIdx.x;
        if (f <= 127)
            compute_frame(logits + ((size_t)(b * NF + f)) * 5, sfr[threadIdx.x]);
    }
    __syncthreads();

    float pos0 = __fmul_rn((float)s0, POSC);
    int i0s = min((int)floorf(pos0), 126);
    int r0i = i0s - f_first;
    int r2i = min(i0s + 2, 127) - f_first;
    float F0[5], F1[5], F2[5];
#pragma unroll
    for (int q = 0; q < 5; q++) { F0[q] = sfr[r0i][q]; F1[q] = sfr[r0i + 1][q]; F2[q] = sfr[r2i][q]; }

    size_t base = (size_t)b * NS + s0;
    float4* aptr = (float4*)(out + 4ull * BS * NS + base * 3);
    float4* bptr = (float4*)(out + 7ull * BS * NS + base * 3);

#pragma unroll
    for (int g = 0; g < 2; g++) {
        float a1v[4], a2v[4], b0v[4], b1v[4], b2v[4];
#pragma unroll
        for (int j = 0; j < 4; j++) {
            int i = s0 + g * 4 + j;
            float pos = __fmul_rn((float)i, POSC);
            int i0 = min((int)floorf(pos), 126);
            float frc = __fsub_rn(pos, (float)i0);
            float w0 = __fsub_rn(1.0f, frc);
            bool hi = (i0 != i0s);
            float fa1 = hi ? F1[0] : F0[0], ga1 = hi ? F2[0] : F1[0];
            float fa2 = hi ? F1[1] : F0[1], ga2 = hi ? F2[1] : F1[1];
            float fb0 = hi ? F1[2] : F0[2], gb0 = hi ? F2[2] : F1[2];
            float fb1 = hi ? F1[3] : F0[3], gb1 = hi ? F2[3] : F1[3];
            float fb2 = hi ? F1[4] : F0[4], gb2 = hi ? F2[4] : F1[4];
            a1v[j] = __fadd_rn(__fmul_rn(fa1, w0), __fmul_rn(ga1, frc));
            a2v[j] = __fadd_rn(__fmul_rn(fa2, w0), __fmul_rn(ga2, frc));
            b0v[j] = __fadd_rn(__fmul_rn(fb0, w0), __fmul_rn(gb0, frc));
            b1v[j] = __fadd_rn(__fmul_rn(fb1, w0), __fmul_rn(gb1, frc));
            b2v[j] = __fadd_rn(__fmul_rn(fb2, w0), __fmul_rn(gb2, frc));
        }
        aptr[3 * g + 0] = make_float4(1.0f, a1v[0], a2v[0], 1.0f);
        aptr[3 * g + 1] = make_float4(a1v[1], a2v[1], 1.0f, a1v[2]);
        aptr[3 * g + 2] = make_float4(a2v[2], 1.0f, a1v[3], a2v[3]);
        bptr[3 * g + 0] = make_float4(b0v[0], b1v[0], b2v[0], b0v[1]);
        bptr[3 * g + 1] = make_float4(b1v[1], b2v[1], b0v[2], b1v[2]);
        bptr[3 * g + 2] = make_float4(b2v[2], b0v[3], b1v[3], b2v[3]);
    }
}

// ---------------- K1: osc + env + a1/a2 interp + fused pass1 ----------------
__global__ void __launch_bounds__(128) k_mainp1(
        float* __restrict__ out,
        const float* __restrict__ f0_hz,
        const float* __restrict__ durp,
        const float* __restrict__ phasep,
        const float* __restrict__ logits,
        const float* __restrict__ shpp,
        const float* __restrict__ gainp,
        const float* __restrict__ alphap) {
    __shared__ float sfr[5][5];
    __shared__ float sbp[12];

    int tid = blockIdx.x * blockDim.x + threadIdx.x;
    int b = tid >> 13;
    int c = tid & (NCH - 1);
    int s0 = c << 3;

    int BS0 = (blockIdx.x & 63) << 10;
    float bpos0 = __fmul_rn((float)BS0, POSC);
    int f_first = min((int)floorf(bpos0), 126);

    if (threadIdx.x < 5) {
        int f = f_first + threadIdx.x;
        if (f <= 127)
            compute_frame(logits + ((size_t)(b * NF + f)) * 5, sfr[threadIdx.x]);
    } else if (threadIdx.x == 5) {
        float f0 = f0_hz[b];
        sbp[0] = __fdiv_rn(f0, SRf);
        sbp[1] = phasep[b];
        float partials = __fdiv_rn(12000.0f, __fmul_rn(f0, log10f(f0)));
        sbp[2] = __fmul_rn(3.14159274101257324f, partials);
        float sh = shpp[b];
        sbp[3] = sh;
        sbp[4] = __fsub_rn(1.0f, __fmul_rn(sh, 0.5f));
        sbp[5] = gainp[b];
        sbp[6] = durp[b];
        sbp[7] = alphap[b];
        sbp[8] = __fdiv_rn(1.0f, durp[b]);
    }
    __syncthreads();

    float p_phase = sbp[1], p_kk = sbp[2], p_shp = sbp[3];
    float p_sm = sbp[4], p_gain = sbp[5], p_dur = sbp[6], p_alpha = sbp[7], p_rdur = sbp[8];

    float pos0 = __fmul_rn((float)s0, POSC);
    int i0s = min((int)floorf(pos0), 126);
    int r0i = i0s - f_first;
    int r2i = min(i0s + 2, 127) - f_first;
    float Fa1_0 = sfr[r0i][0], Fa2_0 = sfr[r0i][1];
    float Fa1_1 = sfr[r0i + 1][0], Fa2_1 = sfr[r0i + 1][1];
    float Fa1_2 = sfr[r2i][0], Fa2_2 = sfr[r2i][1];

    float yp1 = 0.f, yp2 = 0.f, u1 = 1.f, u2 = 0.f, v1 = 0.f, v2 = 1.f;

    float tt0 = div_cr((float)s0, SRf, R48);
    bool alive = (tt0 <= p_dur);

    size_t base = (size_t)b * NS + s0;
    float4* dptr = (float4*)(out + base);
    float4* eptr = (float4*)(out + 2ull * BS * NS + base);

    float inc = sbp[0];
    float i4 = inc * 4.0f, i2c = inc * 2.0f;
    float baseA = 0.0f, baseB = 0.0f;
    if (alive) {
        baseA = (s0 == 0) ? 0.0f : cum_base3(inc, (unsigned)s0);
        baseB = cum_base3(inc, (unsigned)(s0 + 8));
    }

#pragma unroll
    for (int g = 0; g < 2; g++) {
        float dry4[4], env4[4];
#pragma unroll
        for (int j = 0; j < 4; j++) {
            int jj = g * 4 + j;
            int i = s0 + jj;
            if (alive) {
                unsigned l = (unsigned)(jj + 1);
                float cum = (l < 8u) ? baseA : baseB;
                if (l & 4u)  cum = __fadd_rn(cum, i4);
                if (l & 2u)  cum = __fadd_rn(cum, i2c);
                if (l & 1u)  cum = __fadd_rn(cum, inc);
                float arg = __fadd_rn(__fmul_rn(6.28318548202514648f, cum), p_phase);
                float carg = __fmul_rn(arg, 0.5f);
                float kq = rintf(__fmul_rn(carg, 0.15915494309189535f));
                float rr = fmaf(-kq, 6.28318548202514648f, carg);
                float ps, pc; int iq;
                fast_sc(rr, ps, pc, iq);
                float shh = (iq & 1) ? pc : ps; shh = (iq & 2) ? -shh : shh;
                float chh = (iq & 1) ? ps : pc; chh = ((iq + 1) & 2) ? -chh : chh;
                float cc = chh;
                float s = 2.0f * shh * chh;

                float sq = xla_tanh_f(__fmul_rn(__fmul_rn(p_kk, s), 0.5f));
                float vco = __fmul_rn(__fmul_rn(p_sm, sq),
                                      __fadd_rn(1.0f, __fmul_rn(p_shp, cc)));

                float tt = div_cr((float)i, SRf, R48);
                float ramp = __fsub_rn(1.0f, div_cr(tt, p_dur, p_rdur));
                ramp = fminf(fmaxf(ramp, 0.001f), 1.0f);
                float env = __powf(ramp, p_alpha);
                if (!(tt <= p_dur)) env = 0.0f;
                env4[j] = env;
                dry4[j] = __fmul_rn(__fmul_rn(vco, p_gain), env);
            } else {
                env4[j] = 0.0f;
                dry4[j] = 0.0f;
            }

            float pos = __fmul_rn((float)i, POSC);
            int i0 = min((int)floorf(pos), 126);
            float frc = __fsub_rn(pos, (float)i0);
            float w0 = __fsub_rn(1.0f, frc);
            bool hi = (i0 != i0s);
            float fa1 = hi ? Fa1_1 : Fa1_0, ga1 = hi ? Fa1_2 : Fa1_1;
            float fa2 = hi ? Fa2_1 : Fa2_0, ga2 = hi ? Fa2_2 : Fa2_1;
            float a1 = __fadd_rn(__fmul_rn(fa1, w0), __fmul_rn(ga1, frc));
            float a2 = __fadd_rn(__fmul_rn(fa2, w0), __fmul_rn(ga2, frc));

            float dj = dry4[j];
            float yp = fmaf(-a1, yp1, fmaf(-a2, yp2, dj));
            float uu = fmaf(-a1, u1, -(a2 * u2));
            float vv = fmaf(-a1, v1, -(a2 * v2));
            yp2 = yp1; yp1 = yp;
            u2 = u1; u1 = uu;
            v2 = v1; v1 = vv;
        }
        dptr[g] = make_float4(dry4[0], dry4[1], dry4[2], dry4[3]);
        eptr[g] = make_float4(env4[0], env4[1], env4[2], env4[3]);
    }

    float* o = g_chunk + (size_t)tid * 6;
    o[0] = u1; o[1] = v1; o[2] = u2; o[3] = v2; o[4] = yp1; o[5] = yp2;
}

#define COMPOSE_ACC(c00,c01,c10,c11,r0,r1, m00,m01,m10,m11,p0,p1) do { \
    float n00 = __fmaf_rn(c00, m00, __fmul_rn(c01, m10)); \
    float n01 = __fmaf_rn(c00, m01, __fmul_rn(c01, m11)); \
    float n10 = __fmaf_rn(c10, m00, __fmul_rn(c11, m10)); \
    float n11 = __fmaf_rn(c10, m01, __fmul_rn(c11, m11)); \
    float np0 = __fadd_rn(__fmaf_rn(c00, p0, __fmul_rn(c01, p1)), r0); \
    float np1 = __fadd_rn(__fmaf_rn(c10, p0, __fmul_rn(c11, p1)), r1); \
    m00 = n00; m01 = n01; m10 = n10; m11 = n11; p0 = np0; p1 = np1; } while (0)

// ---------------- K2: per-voice parallel scan + g_frame publish ----------------
__global__ void k_scan2(const float* __restrict__ logits) {
    extern __shared__ float sm[];
    __shared__ float wtot[8 * 6];
    __shared__ float wpre[8 * 6];
    int b = blockIdx.x;
    int tid = threadIdx.x;

    const float* raw = g_chunk + (size_t)b * NCH * 6;
    for (int idx = tid; idx < NCH * 6; idx += blockDim.x) {
        int chunk = idx / 6;
        int field = idx - chunk * 6;
        int w = chunk >> 10;
        int chr = chunk & 1023;
        int swp = ((chr & 31) << 5) | (chr >> 5);
        sm[((w << 10) + swp) * 7 + field] = raw[idx];
    }
    if (tid >= 256 && tid < 384) {
        int f = tid - 256;
        float dst[5];
        compute_frame(logits + ((size_t)(b * NF + f)) * 5, dst);
        g_frame[(b * NF + f) * 2]     = make_float4(dst[0], dst[1], dst[2], dst[3]);
        g_frame[(b * NF + f) * 2 + 1] = make_float4(dst[4], 0.f, 0.f, 0.f);
    }
    __syncthreads();

    float m00 = 1.f, m01 = 0.f, m10 = 0.f, m11 = 1.f, p0 = 0.f, p1 = 0.f;
    int w = tid >> 5, lane = tid & 31;
    if (tid < 256) {
        const float* rbase = &sm[(w << 10) * 7 + lane * 7];
#pragma unroll 1
        for (int c = 0; c < 32; c++) {
            const float* rec = rbase + (c << 5) * 7;
            COMPOSE_ACC(rec[0], rec[1], rec[2], rec[3], rec[4], rec[5],
                        m00, m01, m10, m11, p0, p1);
        }
#pragma unroll
        for (int d = 1; d < 32; d <<= 1) {
            float e00 = __shfl_up_sync(0xffffffffu, m00, d);
            float e01 = __shfl_up_sync(0xffffffffu, m01, d);
            float e10 = __shfl_up_sync(0xffffffffu, m10, d);
            float e11 = __shfl_up_sync(0xffffffffu, m11, d);
            float ep0 = __shfl_up_sync(0xffffffffu, p0, d);
            float ep1 = __shfl_up_sync(0xffffffffu, p1, d);
            if (lane >= d) {
                float n00 = __fmaf_rn(m00, e00, __fmul_rn(m01, e10));
                float n01 = __fmaf_rn(m00, e01, __fmul_rn(m01, e11));
                float n10 = __fmaf_rn(m10, e00, __fmul_rn(m11, e10));
                float n11 = __fmaf_rn(m10, e01, __fmul_rn(m11, e11));
                float np0 = __fadd_rn(__fmaf_rn(m00, ep0, __fmul_rn(m01, ep1)), p0);
                float np1 = __fadd_rn(__fmaf_rn(m10, ep0, __fmul_rn(m11, ep1)), p1);
                m00 = n00; m01 = n01; m10 = n10; m11 = n11; p0 = np0; p1 = np1;
            }
        }
        if (lane == 31) {
            wtot[w * 6 + 0] = m00; wtot[w * 6 + 1] = m01; wtot[w * 6 + 2] = m10;
            wtot[w * 6 + 3] = m11; wtot[w * 6 + 4] = p0;  wtot[w * 6 + 5] = p1;
        }
    }
    __syncthreads();
    if (tid == 0) {
        float q00 = 1.f, q01 = 0.f, q10 = 0.f, q11 = 1.f, qp0 = 0.f, qp1 = 0.f;
#pragma unroll
        for (int ww = 0; ww < 8; ww++) {
            wpre[ww * 6 + 0] = q00; wpre[ww * 6 + 1] = q01; wpre[ww * 6 + 2] = q10;
            wpre[ww * 6 + 3] = q11; wpre[ww * 6 + 4] = qp0; wpre[ww * 6 + 5] = qp1;
            COMPOSE_ACC(wtot[ww * 6 + 0], wtot[ww * 6 + 1], wtot[ww * 6 + 2],
                        wtot[ww * 6 + 3], wtot[ww * 6 + 4], wtot[ww * 6 + 5],
                        q00, q01, q10, q11, qp0, qp1);
        }
    }
    __syncthreads();
    if (tid < 256) {
        float e00 = __shfl_up_sync(0xffffffffu, m00, 1);
        float e01 = __shfl_up_sync(0xffffffffu, m01, 1);
        float e10 = __shfl_up_sync(0xffffffffu, m10, 1);
        float e11 = __shfl_up_sync(0xffffffffu, m11, 1);
        float ep0 = __shfl_up_sync(0xffffffffu, p0, 1);
        float ep1 = __shfl_up_sync(0xffffffffu, p1, 1);
        if (lane == 0) { e00 = 1.f; e01 = 0.f; e10 = 0.f; e11 = 1.f; ep0 = 0.f; ep1 = 0.f; }
        float Pp0 = wpre[w * 6 + 4], Pp1 = wpre[w * 6 + 5];
        float s0 = __fadd_rn(__fmaf_rn(e00, Pp0, __fmul_rn(e01, Pp1)), ep0);
        float s1 = __fadd_rn(__fmaf_rn(e10, Pp0, __fmul_rn(e11, Pp1)), ep1);

        const float* rbase = &sm[(w << 10) * 7 + lane * 7];
        int cbase = (b << 13) + tid * 32;
#pragma unroll 1
        for (int c = 0; c < 32; c++) {
            g_init[cbase + c] = make_float2(s0, s1);
            const float* rec = rbase + (c << 5) * 7;
            float ns0 = __fadd_rn(__fmaf_rn(rec[0], s0, __fmul_rn(rec[1], s1)), rec[4]);
            float ns1 = __fadd_rn(__fmaf_rn(rec[2], s0, __fmul_rn(rec[3], s1)), rec[5]);
            s0 = ns0; s1 = ns1;
        }
    }
}

// ---------------- K3: pass 2 — coeff recompute + IIR + FIR + tanh (lean) ----------------
__global__ void __launch_bounds__(128) k_pass2(float* __restrict__ out,
                                               const float* __restrict__ distp) {
    int tid = blockIdx.x * blockDim.x + threadIdx.x;
    if (tid >= BS * NCH) return;
    int b = tid >> 13;
    int c = tid & (NCH - 1);
    int s0 = c << 3;
    size_t base = (size_t)b * NS + s0;
    const float* dry = out + base;
    float* w_wet = out + 1ull * BS * NS + base;
    float* w_yab = out + 3ull * BS * NS + base;
    float* w_ya = out + 10ull * BS * NS + base;

    float pos0 = __fmul_rn((float)s0, POSC);
    int i0s = min((int)floorf(pos0), 126);
    int i2x = min(i0s + 2, 127);
    float4 F0a = g_frame[(b * NF + i0s) * 2],     F0b = g_frame[(b * NF + i0s) * 2 + 1];
    float4 F1a = g_frame[(b * NF + i0s + 1) * 2], F1b = g_frame[(b * NF + i0s + 1) * 2 + 1];
    float4 F2a = g_frame[(b * NF + i2x) * 2],     F2b = g_frame[(b * NF + i2x) * 2 + 1];

    float2 ini = g_init[tid];
    float y1 = ini.x, y2 = ini.y;
    float dg = distp[b];

#pragma unroll
    for (int g = 0; g < 2; g++) {
        float4 xq = ((const float4*)dry)[g];
        float xs[4] = {xq.x, xq.y, xq.z, xq.w};
        float ya[4], yb[4], wt[4];
#pragma unroll
        for (int j = 0; j < 4; j++) {
            int i = s0 + g * 4 + j;
            float pos = __fmul_rn((float)i, POSC);
            int i0 = min((int)floorf(pos), 126);
            float frc = __fsub_rn(pos, (float)i0);
            float w0 = __fsub_rn(1.0f, frc);
            bool hi = (i0 != i0s);
            float4 fA = hi ? F1a : F0a;
            float4 fB = hi ? F1b : F0b;
            float4 gA = hi ? F2a : F1a;
            float4 gB = hi ? F2b : F1b;
            float a1 = __fadd_rn(__fmul_rn(fA.x, w0), __fmul_rn(gA.x, frc));
            float a2 = __fadd_rn(__fmul_rn(fA.y, w0), __fmul_rn(gA.y, frc));
            float c0 = __fadd_rn(__fmul_rn(fA.z, w0), __fmul_rn(gA.z, frc));
            float c1 = __fadd_rn(__fmul_rn(fA.w, w0), __fmul_rn(gA.w, frc));
            float c2 = __fadd_rn(__fmul_rn(fB.x, w0), __fmul_rn(gB.x, frc));

            float y = __fsub_rn(__fsub_rn(xs[j], __fmul_rn(a1, y1)), __fmul_rn(a2, y2));
            float v = __fadd_rn(__fadd_rn(__fmul_rn(c0, y), __fmul_rn(c1, y1)),
                                __fmul_rn(c2, y2));
            ya[j] = y; yb[j] = v;
            wt[j] = xla_tanh_f(__fmul_rn(v, dg));
            y2 = y1; y1 = y;
        }
        ((float4*)w_ya)[g] = make_float4(ya[0], ya[1], ya[2], ya[3]);
        ((float4*)w_yab)[g] = make_float4(yb[0], yb[1], yb[2], yb[3]);
        ((float4*)w_wet)[g] = make_float4(wt[0], wt[1], wt[2], wt[3]);
    }
}

extern "C" void kernel_launch(void* const* d_in, const int* in_sizes, int n_in,
                              void* d_out, int out_size) {
    const float* f0_hz = (const float*)d_in[0];
    const float* note_on = (const float*)d_in[1];
    const float* phase = (const float*)d_in[2];
    const float* logits = (const float*)d_in[3];
    const float* osc_shape = (const float*)d_in[4];
    const float* osc_gain = (const float*)d_in[5];
    const float* dist_gain = (const float*)d_in[6];
    const float* learned_alpha = (const float*)d_in[7];
    float* out = (float*)d_out;

    static int inited = 0;
    static cudaStream_t s2;
    static cudaEvent_t evFork, evJoin;
    const int scan_smem = NCH * 7 * sizeof(float);   // 229376 B dynamic
    if (!inited) {
        cudaFuncSetAttribute(k_scan2, cudaFuncAttributeMaxDynamicSharedMemorySize, scan_smem);
        cudaStreamCreateWithFlags(&s2, cudaStreamNonBlocking);
        cudaEventCreateWithFlags(&evFork, cudaEventDisableTiming);
        cudaEventCreateWithFlags(&evJoin, cudaEventDisableTiming);
        inited = 1;
    }

    k_mainp1<<<(BS * NCH + 127) / 128, 128>>>(out, f0_hz, note_on, phase, logits,
                                              osc_shape, osc_gain, learned_alpha);

    // fork AFTER mainp1: k_coeff fills a3/b3 planes on the ~120 SMs the
    // 32-block scan leaves idle (and overlaps pass2's start if it runs long)
    cudaEventRecord(evFork, 0);
    cudaStreamWaitEvent(s2, evFork, 0);
    k_coeff<<<(BS * NCH + 127) / 128, 128, 0, s2>>>(out, logits);
    cudaEventRecord(evJoin, s2);

    k_scan2<<<BS, 1024, scan_smem>>>(logits);
    k_pass2<<<(BS * NCH + 127) / 128, 128>>>(out, dist_gain);

    // join so the graph completes only after the coeff planes are written
    cudaStreamWaitEvent(0, evJoin, 0);
}